// round 9
// baseline (speedup 1.0000x reference)
#include <cuda_runtime.h>

// BiMamba: bidirectional mamba block.
//   x: (8, 256, 2048)  -> out: (8, 512, 2048)
// Big GEMMs (in-proj / out-proj) on tensor cores via split-bf16 (3-term) mma.
// R9 = R6 (proven passing) + fused xproj+delta ONLY (bisecting the R7/R8 delta).
#define LSEQ   2048
#define DMODEL 256
#define DINNER 512
#define NST    16
#define NB     8
#define MROWS  (NB * LSEQ)   // 16384 rows per direction

// ---------------- scratch (device globals; no allocation allowed) -----------
__device__ float g_xi   [2u * MROWS * DINNER];  // K1 out (l-major) ; later yT (d-major)
__device__ float g_sz   [2u * MROWS * DINNER];  // silu(z)
__device__ float g_xc   [2u * MROWS * DINNER];  // conv output (silu'd)
__device__ float g_xdbl [2u * MROWS * 48];      // [unused(16) | B(16) | C(16)]
__device__ float g_delta[2u * MROWS * DINNER];  // softplus(dt @ dt_w^T + dt_b)

// split-bf16 weights (hi/lo), k-major rows
__device__ unsigned short g_wih[2][1024 * 256];  // in_w hi
__device__ unsigned short g_wil[2][1024 * 256];  // in_w lo
__device__ unsigned short g_woh[2][256 * 512];   // out_w hi
__device__ unsigned short g_wol[2][256 * 512];   // out_w lo

__device__ __forceinline__ float sigmoidf_(float v) {
    return __fdividef(1.0f, 1.0f + __expf(-v));
}

// hi = truncate-to-bf16 (exact residual), lo = rn-bf16 of residual
__device__ __forceinline__ void splitf_(float v, unsigned short& h, unsigned short& l) {
    unsigned u = __float_as_uint(v);
    unsigned hb = u & 0xFFFF0000u;
    h = (unsigned short)(hb >> 16);
    float r = v - __uint_as_float(hb);
    unsigned ur = __float_as_uint(r);
    l = (unsigned short)((ur + 0x7FFFu + ((ur >> 16) & 1u)) >> 16);
}

__device__ __forceinline__ void mma_bf16_(float* C, const unsigned* A, const unsigned* B) {
    asm volatile(
        "mma.sync.aligned.m16n8k16.row.col.f32.bf16.bf16.f32 "
        "{%0,%1,%2,%3},{%4,%5,%6,%7},{%8,%9},{%0,%1,%2,%3};\n"
        : "+f"(C[0]), "+f"(C[1]), "+f"(C[2]), "+f"(C[3])
        : "r"(A[0]), "r"(A[1]), "r"(A[2]), "r"(A[3]), "r"(B[0]), "r"(B[1]));
}

// ---------------- K0: weight split prepass ----------------------------------
// blockIdx.y selects tensor: 0=f_in_w, 1=b_in_w, 2=f_out_w, 3=b_out_w
__global__ __launch_bounds__(256) void cvt_split_all(
    const float* __restrict__ fin, const float* __restrict__ bin,
    const float* __restrict__ fout, const float* __restrict__ bout)
{
    const int which = blockIdx.y;
    const float* __restrict__ src;
    unsigned short *hi, *lo;
    int n4;
    if (which == 0)      { src = fin;  hi = g_wih[0]; lo = g_wil[0]; n4 = 65536; }
    else if (which == 1) { src = bin;  hi = g_wih[1]; lo = g_wil[1]; n4 = 65536; }
    else if (which == 2) { src = fout; hi = g_woh[0]; lo = g_wol[0]; n4 = 32768; }
    else                 { src = bout; hi = g_woh[1]; lo = g_wol[1]; n4 = 32768; }

    int i = blockIdx.x * 256 + threadIdx.x;
    if (i >= n4) return;
    float4 v = reinterpret_cast<const float4*>(src)[i];
    unsigned short h0, h1, h2, h3, q0, q1, q2, q3;
    splitf_(v.x, h0, q0); splitf_(v.y, h1, q1);
    splitf_(v.z, h2, q2); splitf_(v.w, h3, q3);
    reinterpret_cast<uint2*>(hi)[i] =
        make_uint2((unsigned)h0 | ((unsigned)h1 << 16), (unsigned)h2 | ((unsigned)h3 << 16));
    reinterpret_cast<uint2*>(lo)[i] =
        make_uint2((unsigned)q0 | ((unsigned)q1 << 16), (unsigned)q2 | ((unsigned)q3 << 16));
}

// ---------------- K1: in-projection (tensor core) ---------------------------
// C[m,e] = sum_k X[m,k] W[e,k]; X[m=(b,l),k] = x[b,k, l or L-1-l]
// e<512 -> g_xi ; e>=512 -> g_sz = silu(val)
__global__ __launch_bounds__(256) void gemm_in_tc(const float* __restrict__ x)
{
    const int dir = blockIdx.z;
    const int m0 = blockIdx.y * 128;
    const int n0 = blockIdx.x * 128;
    const int b  = m0 >> 11;
    const int l0 = m0 & (LSEQ - 1);
    const unsigned short* __restrict__ Wh = g_wih[dir];
    const unsigned short* __restrict__ Wl = g_wil[dir];
    const float* __restrict__ xb = x + (size_t)b * DMODEL * LSEQ;

    // A pre-packed by k-pairs: Ahp[k2][m] = bf16(A[2k2][m]) | bf16(A[2k2+1][m])<<16
    __shared__ unsigned Ahp[16][136], Alp[16][136];
    __shared__ unsigned Bhp[128][20], Blp[128][20];   // [n][k2], 16 k2 + pad

    const int tid = threadIdx.x;
    const int warp = tid >> 5, lane = tid & 31;
    const int wm = (warp & 3) * 32, wn = (warp >> 2) * 64;
    const int grp = lane >> 2, qid = lane & 3;

    float c[2][8][4];
#pragma unroll
    for (int mi = 0; mi < 2; mi++)
#pragma unroll
        for (int ni = 0; ni < 8; ni++)
#pragma unroll
            for (int r = 0; r < 4; r++) c[mi][ni][r] = 0.f;

    const int ak2   = tid >> 4;          // 0..15
    const int amseg = (tid & 15) * 8;    // 0..120
    const int bnrow = tid >> 1;          // 0..127
    const int bkseg = (tid & 1) * 8;     // k2 offset 0 or 8

    for (int k0 = 0; k0 < DMODEL; k0 += 32) {
        // ---- A tile: fp32 -> split bf16, packed k-pairs ----
        const float* srcE = xb + (size_t)(k0 + 2 * ak2) * LSEQ;
        const float* srcO = srcE + LSEQ;
#pragma unroll
        for (int j = 0; j < 2; j++) {
            int mofs = amseg + j * 4;
            float4 ve, vo;
            if (dir == 0) {
                ve = *reinterpret_cast<const float4*>(srcE + l0 + mofs);
                vo = *reinterpret_cast<const float4*>(srcO + l0 + mofs);
            } else {
                float4 re = *reinterpret_cast<const float4*>(srcE + (LSEQ - 4) - (l0 + mofs));
                float4 ro = *reinterpret_cast<const float4*>(srcO + (LSEQ - 4) - (l0 + mofs));
                ve = make_float4(re.w, re.z, re.y, re.x);
                vo = make_float4(ro.w, ro.z, ro.y, ro.x);
            }
            unsigned short he[4], le[4], ho[4], lo_[4];
            splitf_(ve.x, he[0], le[0]); splitf_(ve.y, he[1], le[1]);
            splitf_(ve.z, he[2], le[2]); splitf_(ve.w, he[3], le[3]);
            splitf_(vo.x, ho[0], lo_[0]); splitf_(vo.y, ho[1], lo_[1]);
            splitf_(vo.z, ho[2], lo_[2]); splitf_(vo.w, ho[3], lo_[3]);
            uint4 ph, pl;
            ph.x = (unsigned)he[0] | ((unsigned)ho[0] << 16);
            ph.y = (unsigned)he[1] | ((unsigned)ho[1] << 16);
            ph.z = (unsigned)he[2] | ((unsigned)ho[2] << 16);
            ph.w = (unsigned)he[3] | ((unsigned)ho[3] << 16);
            pl.x = (unsigned)le[0] | ((unsigned)lo_[0] << 16);
            pl.y = (unsigned)le[1] | ((unsigned)lo_[1] << 16);
            pl.z = (unsigned)le[2] | ((unsigned)lo_[2] << 16);
            pl.w = (unsigned)le[3] | ((unsigned)lo_[3] << 16);
            *reinterpret_cast<uint4*>(&Ahp[ak2][mofs]) = ph;
            *reinterpret_cast<uint4*>(&Alp[ak2][mofs]) = pl;
        }
        // ---- B tile: bf16 copy (already k-pair packed in memory) ----
        {
            const unsigned short* wh = Wh + (size_t)(n0 + bnrow) * DMODEL + k0 + bkseg * 2;
            const unsigned short* wl = Wl + (size_t)(n0 + bnrow) * DMODEL + k0 + bkseg * 2;
            *reinterpret_cast<uint4*>(&Bhp[bnrow][bkseg]) = *reinterpret_cast<const uint4*>(wh);
            *reinterpret_cast<uint4*>(&Bhp[bnrow][bkseg + 4]) = *reinterpret_cast<const uint4*>(wh + 8);
            *reinterpret_cast<uint4*>(&Blp[bnrow][bkseg]) = *reinterpret_cast<const uint4*>(wl);
            *reinterpret_cast<uint4*>(&Blp[bnrow][bkseg + 4]) = *reinterpret_cast<const uint4*>(wl + 8);
        }
        __syncthreads();
#pragma unroll
        for (int kk = 0; kk < 2; kk++) {             // two k16 chunks
            const int kq = kk * 8 + qid;             // k2 index of frag cols
            unsigned bh[8][2], bl[8][2];
#pragma unroll
            for (int ni = 0; ni < 8; ni++) {
                int n = wn + ni * 8 + grp;
                bh[ni][0] = Bhp[n][kq];     bh[ni][1] = Bhp[n][kq + 4];
                bl[ni][0] = Blp[n][kq];     bl[ni][1] = Blp[n][kq + 4];
            }
#pragma unroll
            for (int mi = 0; mi < 2; mi++) {
                int m = wm + mi * 16 + grp;
                unsigned ah[4], al[4];
                ah[0] = Ahp[kq][m];     ah[1] = Ahp[kq][m + 8];
                ah[2] = Ahp[kq + 4][m]; ah[3] = Ahp[kq + 4][m + 8];
                al[0] = Alp[kq][m];     al[1] = Alp[kq][m + 8];
                al[2] = Alp[kq + 4][m]; al[3] = Alp[kq + 4][m + 8];
#pragma unroll
                for (int ni = 0; ni < 8; ni++) mma_bf16_(c[mi][ni], ah, bh[ni]);
#pragma unroll
                for (int ni = 0; ni < 8; ni++) mma_bf16_(c[mi][ni], ah, bl[ni]);
#pragma unroll
                for (int ni = 0; ni < 8; ni++) mma_bf16_(c[mi][ni], al, bh[ni]);
            }
        }
        __syncthreads();
    }

    const size_t base = (size_t)dir * MROWS;
#pragma unroll
    for (int mi = 0; mi < 2; mi++) {
        int m = m0 + wm + mi * 16 + grp;
#pragma unroll
        for (int ni = 0; ni < 8; ni++) {
            int n = n0 + wn + ni * 8 + qid * 2;
            float v0 = c[mi][ni][0], v1 = c[mi][ni][1];
            float v2 = c[mi][ni][2], v3 = c[mi][ni][3];
            if (n < DINNER) {
                *reinterpret_cast<float2*>(&g_xi[(base + m) * DINNER + n]) = make_float2(v0, v1);
                *reinterpret_cast<float2*>(&g_xi[(base + m + 8) * DINNER + n]) = make_float2(v2, v3);
            } else {
                int e = n - DINNER;
                *reinterpret_cast<float2*>(&g_sz[(base + m) * DINNER + e]) =
                    make_float2(v0 * sigmoidf_(v0), v1 * sigmoidf_(v1));
                *reinterpret_cast<float2*>(&g_sz[(base + m + 8) * DINNER + e]) =
                    make_float2(v2 * sigmoidf_(v2), v3 * sigmoidf_(v3));
            }
        }
    }
}

// ---------------- K2: causal depthwise conv (k=4) + bias + silu -------------
__global__ __launch_bounds__(512) void conv_silu_kernel(
    const float* __restrict__ cwf, const float* __restrict__ cbf,
    const float* __restrict__ cwb, const float* __restrict__ cbb)
{
    const int dir = blockIdx.z;
    const int b   = blockIdx.y;
    const int l0  = blockIdx.x * 256;
    const int d   = threadIdx.x;
    const float* cw = dir ? cwb : cwf;
    const float* cb = dir ? cbb : cbf;
    const float w0 = cw[d * 4 + 0], w1 = cw[d * 4 + 1];
    const float w2 = cw[d * 4 + 2], w3 = cw[d * 4 + 3];
    const float bias = cb[d];

    const size_t rowbase = ((size_t)dir * MROWS + (size_t)b * LSEQ);
    const float* __restrict__ xip = g_xi + rowbase * DINNER + d;
    float* __restrict__ xcp = g_xc + rowbase * DINNER + d;

    float xm3 = (l0 >= 3) ? xip[(size_t)(l0 - 3) * DINNER] : 0.f;
    float xm2 = (l0 >= 2) ? xip[(size_t)(l0 - 2) * DINNER] : 0.f;
    float xm1 = (l0 >= 1) ? xip[(size_t)(l0 - 1) * DINNER] : 0.f;
    for (int ll = l0; ll < l0 + 256; ll++) {
        float xc = xip[(size_t)ll * DINNER];
        float v = fmaf(w0, xm3, fmaf(w1, xm2, fmaf(w2, xm1, fmaf(w3, xc, bias))));
        xcp[(size_t)ll * DINNER] = v * sigmoidf_(v);
        xm3 = xm2; xm2 = xm1; xm1 = xc;
    }
}

// ---------------- K3: fused x_proj GEMM + delta -----------------------------
// Phase 1: x_dbl[m, 0..47] = xc @ xproj_w^T  (dt cols kept in smem, B/C -> gmem)
// Phase 2: delta[m, d] = softplus(dt @ dt_w^T + dt_b)
__global__ __launch_bounds__(256) void xproj_delta_kernel(
    const float* __restrict__ xwf, const float* __restrict__ xwb,
    const float* __restrict__ dtwf, const float* __restrict__ dtbf,
    const float* __restrict__ dtwb, const float* __restrict__ dtbb)
{
    const int dir = blockIdx.z;
    const float* __restrict__ W   = dir ? xwb : xwf;
    const float* __restrict__ dtw = dir ? dtwb : dtwf;
    const float* __restrict__ dtb = dir ? dtbb : dtbf;
    const int m0 = blockIdx.x * 128;

    __shared__ float sbuf[11264];        // 44 KB, phase-aliased
    float* As  = sbuf;                   // [128][17] = 2176   (phase 1)
    float* Bs  = sbuf + 2176;            // [16][49]  = 784    (phase 1)
    float* dtW = sbuf;                   // [512][17] = 8704   (phase 2)
    float* sB  = sbuf + 8704;            // [512]              (phase 2)
    float* sdt = sbuf + 9216;            // [128][16] = 2048   (disjoint from phase 1)

    const int tid = threadIdx.x;
    const int ty = tid >> 4, tx = tid & 15;

    float acc[8][3];
#pragma unroll
    for (int i = 0; i < 8; i++)
#pragma unroll
        for (int j = 0; j < 3; j++) acc[i][j] = 0.f;

    const size_t abase = ((size_t)dir * MROWS + m0) * DINNER;
    for (int k0 = 0; k0 < DINNER; k0 += 16) {
#pragma unroll
        for (int j = 0; j < 8; j++) {
            int flat = tid + j * 256;
            int ml = flat >> 4, kk = flat & 15;
            As[ml * 17 + kk] = g_xc[abase + (size_t)ml * DINNER + (k0 + kk)];
        }
#pragma unroll
        for (int j = 0; j < 3; j++) {
            int flat = tid + j * 256;
            int e = flat >> 4, kk = flat & 15;
            Bs[kk * 49 + e] = W[(size_t)e * DINNER + (k0 + kk)];
        }
        __syncthreads();
#pragma unroll
        for (int kk = 0; kk < 16; kk++) {
            float av[8], bv[3];
#pragma unroll
            for (int i = 0; i < 8; i++) av[i] = As[(ty * 8 + i) * 17 + kk];
#pragma unroll
            for (int j = 0; j < 3; j++) bv[j] = Bs[kk * 49 + tx * 3 + j];
#pragma unroll
            for (int i = 0; i < 8; i++)
#pragma unroll
                for (int j = 0; j < 3; j++)
                    acc[i][j] = fmaf(av[i], bv[j], acc[i][j]);
        }
        __syncthreads();
    }

    // dt (cols 0..15) -> sdt ; B/C (cols 16..47) -> gmem
#pragma unroll
    for (int i = 0; i < 8; i++) {
#pragma unroll
        for (int j = 0; j < 3; j++) {
            int col = tx * 3 + j;
            if (col < 16)
                sdt[(ty * 8 + i) * 16 + col] = acc[i][j];
            else
                g_xdbl[((size_t)dir * MROWS + m0 + ty * 8 + i) * 48 + col] = acc[i][j];
        }
    }
    // load dt_w (padded 17) + bias; overwrites As/Bs (all reads done)
#pragma unroll
    for (int i = 0; i < 32; i++) {
        int flat = tid + i * 256;            // 8192 = 512*16
        dtW[(flat >> 4) * 17 + (flat & 15)] = dtw[flat];
    }
#pragma unroll
    for (int i = 0; i < 2; i++) sB[tid + i * 256] = dtb[tid + i * 256];
    __syncthreads();

    const int d = tid & 255;                 // two d per thread: d, d+256
    float* __restrict__ outp = g_delta + ((size_t)dir * MROWS + m0) * DINNER;
#pragma unroll 2
    for (int ml = 0; ml < 128; ml++) {
        const float* __restrict__ dtrow = sdt + ml * 16;
#pragma unroll
        for (int half = 0; half < 2; half++) {
            int dd = d + half * 256;
            float a = sB[dd];
            const float* __restrict__ wrow = dtW + dd * 17;
#pragma unroll
            for (int r = 0; r < 16; r++)
                a = fmaf(dtrow[r], wrow[r], a);
            float sp = (a > 15.f) ? a : log1pf(__expf(a));
            outp[(size_t)ml * DINNER + dd] = sp;
        }
    }
}

// ---------------- K5: selective scan ----------------------------------------
// 4 threads per (dir,b,d) channel, 4 states each; B/C chunk-staged in smem.
// Writes yT (aliased onto g_xi) in d-major layout.
__global__ __launch_bounds__(128) void scan_kernel(
    const float* __restrict__ Alf, const float* __restrict__ Df,
    const float* __restrict__ Alb, const float* __restrict__ Db)
{
    const int bi   = blockIdx.x;         // 256 blocks: dir(2) x b(8) x dblk(16)
    const int dir  = bi >> 7;
    const int b    = (bi >> 4) & 7;
    const int dblk = bi & 15;
    const int tid  = threadIdx.x;
    const int w    = tid >> 5;
    const int lane = tid & 31;
    const int q    = lane >> 3;
    const int dlo  = lane & 7;
    const int d    = dblk * 32 + w * 8 + dlo;

    const float* Al = dir ? Alb : Alf;
    const float* Dp = dir ? Db : Df;

    float A[4];
#pragma unroll
    for (int n = 0; n < 4; n++) A[n] = -__expf(Al[d * NST + q * 4 + n]);
    const float Dd = Dp[d];

    float h[4];
#pragma unroll
    for (int n = 0; n < 4; n++) h[n] = 0.f;

    const size_t mb = (size_t)dir * MROWS + (size_t)b * LSEQ;
    const float* __restrict__ dl  = g_delta + mb * DINNER + d;
    const float* __restrict__ xp  = g_xc    + mb * DINNER + d;
    const float* __restrict__ szp = g_sz    + mb * DINNER + d;
    float* __restrict__ yTp = g_xi + ((size_t)(dir * DINNER + d) * NB + b) * LSEQ;
    const float* __restrict__ bc  = g_xdbl  + mb * 48 + 16;

    __shared__ float sBC[64][32];

    float dcur = dl[0], xcur = xp[0], szcur = szp[0];
    float yb4[4];

    for (int t0 = 0; t0 < LSEQ; t0 += 64) {
        __syncthreads();
#pragma unroll
        for (int i = 0; i < 16; i++) {
            int flat = tid + i * 128;
            int tt = flat >> 5, j = flat & 31;
            sBC[tt][j] = bc[(size_t)(t0 + tt) * 48 + j];
        }
        __syncthreads();
#pragma unroll 4
        for (int t = 0; t < 64; t++) {
            const int tg = t0 + t;
            const int tn = (tg + 1 < LSEQ) ? (tg + 1) : tg;
            float dn  = dl[(size_t)tn * DINNER];
            float xn  = xp[(size_t)tn * DINNER];
            float szn = szp[(size_t)tn * DINNER];

            float4 Bv = *reinterpret_cast<const float4*>(&sBC[t][q * 4]);
            float4 Cv = *reinterpret_cast<const float4*>(&sBC[t][16 + q * 4]);

            const float dx = dcur * xcur;
            float y;
            h[0] = fmaf(__expf(dcur * A[0]), h[0], dx * Bv.x); y = h[0] * Cv.x;
            h[1] = fmaf(__expf(dcur * A[1]), h[1], dx * Bv.y); y = fmaf(h[1], Cv.y, y);
            h[2] = fmaf(__expf(dcur * A[2]), h[2], dx * Bv.z); y = fmaf(h[2], Cv.z, y);
            h[3] = fmaf(__expf(dcur * A[3]), h[3], dx * Bv.w); y = fmaf(h[3], Cv.w, y);

            y += __shfl_xor_sync(0xFFFFFFFFu, y, 8);
            y += __shfl_xor_sync(0xFFFFFFFFu, y, 16);

            yb4[t & 3] = (y + xcur * Dd) * szcur;
            if ((t & 3) == 3 && q == 0) {
                *reinterpret_cast<float4*>(&yTp[tg - 3]) =
                    make_float4(yb4[0], yb4[1], yb4[2], yb4[3]);
            }
            dcur = dn; xcur = xn; szcur = szn;
        }
    }
}

// ---------------- K6: out-projection (tensor core) + un-flip + concat -------
// out[b, dir*256+o, l_phys] = sum_d yT[d, b, l] * W[o, d]
__global__ __launch_bounds__(256) void gemm_out_tc(float* __restrict__ out)
{
    const int dir = blockIdx.z;
    const int m0 = blockIdx.y * 128;
    const int n0 = blockIdx.x * 128;
    const int b  = m0 >> 11;
    const int l0 = m0 & (LSEQ - 1);
    const unsigned short* __restrict__ Wh = g_woh[dir];
    const unsigned short* __restrict__ Wl = g_wol[dir];

    __shared__ unsigned Ahp[16][136], Alp[16][136];
    __shared__ unsigned Bhp[128][20], Blp[128][20];

    const int tid = threadIdx.x;
    const int warp = tid >> 5, lane = tid & 31;
    const int wm = (warp & 3) * 32, wn = (warp >> 2) * 64;
    const int grp = lane >> 2, qid = lane & 3;

    float c[2][8][4];
#pragma unroll
    for (int mi = 0; mi < 2; mi++)
#pragma unroll
        for (int ni = 0; ni < 8; ni++)
#pragma unroll
            for (int r = 0; r < 4; r++) c[mi][ni][r] = 0.f;

    const int ak2   = tid >> 4;
    const int amseg = (tid & 15) * 8;
    const int bnrow = tid >> 1;
    const int bkseg = (tid & 1) * 8;

    for (int k0 = 0; k0 < DINNER; k0 += 32) {
        const float* srcE = g_xi +
            ((size_t)(dir * DINNER + k0 + 2 * ak2) * NB + b) * LSEQ + l0;
        const float* srcO = srcE + (size_t)NB * LSEQ;
#pragma unroll
        for (int j = 0; j < 2; j++) {
            int mofs = amseg + j * 4;
            float4 ve = *reinterpret_cast<const float4*>(srcE + mofs);
            float4 vo = *reinterpret_cast<const float4*>(srcO + mofs);
            unsigned short he[4], le[4], ho[4], lo_[4];
            splitf_(ve.x, he[0], le[0]); splitf_(ve.y, he[1], le[1]);
            splitf_(ve.z, he[2], le[2]); splitf_(ve.w, he[3], le[3]);
            splitf_(vo.x, ho[0], lo_[0]); splitf_(vo.y, ho[1], lo_[1]);
            splitf_(vo.z, ho[2], lo_[2]); splitf_(vo.w, ho[3], lo_[3]);
            uint4 ph, pl;
            ph.x = (unsigned)he[0] | ((unsigned)ho[0] << 16);
            ph.y = (unsigned)he[1] | ((unsigned)ho[1] << 16);
            ph.z = (unsigned)he[2] | ((unsigned)ho[2] << 16);
            ph.w = (unsigned)he[3] | ((unsigned)ho[3] << 16);
            pl.x = (unsigned)le[0] | ((unsigned)lo_[0] << 16);
            pl.y = (unsigned)le[1] | ((unsigned)lo_[1] << 16);
            pl.z = (unsigned)le[2] | ((unsigned)lo_[2] << 16);
            pl.w = (unsigned)le[3] | ((unsigned)lo_[3] << 16);
            *reinterpret_cast<uint4*>(&Ahp[ak2][mofs]) = ph;
            *reinterpret_cast<uint4*>(&Alp[ak2][mofs]) = pl;
        }
        {
            const unsigned short* wh = Wh + (size_t)(n0 + bnrow) * DINNER + k0 + bkseg * 2;
            const unsigned short* wl = Wl + (size_t)(n0 + bnrow) * DINNER + k0 + bkseg * 2;
            *reinterpret_cast<uint4*>(&Bhp[bnrow][bkseg]) = *reinterpret_cast<const uint4*>(wh);
            *reinterpret_cast<uint4*>(&Bhp[bnrow][bkseg + 4]) = *reinterpret_cast<const uint4*>(wh + 8);
            *reinterpret_cast<uint4*>(&Blp[bnrow][bkseg]) = *reinterpret_cast<const uint4*>(wl);
            *reinterpret_cast<uint4*>(&Blp[bnrow][bkseg + 4]) = *reinterpret_cast<const uint4*>(wl + 8);
        }
        __syncthreads();
#pragma unroll
        for (int kk = 0; kk < 2; kk++) {
            const int kq = kk * 8 + qid;
            unsigned bh[8][2], bl[8][2];
#pragma unroll
            for (int ni = 0; ni < 8; ni++) {
                int n = wn + ni * 8 + grp;
                bh[ni][0] = Bhp[n][kq];     bh[ni][1] = Bhp[n][kq + 4];
                bl[ni][0] = Blp[n][kq];     bl[ni][1] = Blp[n][kq + 4];
            }
#pragma unroll
            for (int mi = 0; mi < 2; mi++) {
                int m = wm + mi * 16 + grp;
                unsigned ah[4], al[4];
                ah[0] = Ahp[kq][m];     ah[1] = Ahp[kq][m + 8];
                ah[2] = Ahp[kq + 4][m]; ah[3] = Ahp[kq + 4][m + 8];
                al[0] = Alp[kq][m];     al[1] = Alp[kq][m + 8];
                al[2] = Alp[kq + 4][m]; al[3] = Alp[kq + 4][m + 8];
#pragma unroll
                for (int ni = 0; ni < 8; ni++) mma_bf16_(c[mi][ni], ah, bh[ni]);
#pragma unroll
                for (int ni = 0; ni < 8; ni++) mma_bf16_(c[mi][ni], ah, bl[ni]);
#pragma unroll
                for (int ni = 0; ni < 8; ni++) mma_bf16_(c[mi][ni], al, bh[ni]);
            }
        }
        __syncthreads();
    }

#pragma unroll
    for (int mi = 0; mi < 2; mi++) {
        int l = l0 + wm + mi * 16 + grp;
        int lp0 = dir ? (LSEQ - 1 - l) : l;
        int lp1 = dir ? (LSEQ - 1 - (l + 8)) : (l + 8);
#pragma unroll
        for (int ni = 0; ni < 8; ni++) {
            int o = n0 + wn + ni * 8 + qid * 2;
            float* op0 = out + ((size_t)b * (2 * DMODEL) + dir * DMODEL + o) * LSEQ;
            float* op1 = op0 + LSEQ;
            op0[lp0] = c[mi][ni][0];
            op1[lp0] = c[mi][ni][1];
            op0[lp1] = c[mi][ni][2];
            op1[lp1] = c[mi][ni][3];
        }
    }
}

// ---------------- launch -----------------------------------------------------
extern "C" void kernel_launch(void* const* d_in, const int* in_sizes, int n_in,
                              void* d_out, int out_size)
{
    (void)in_sizes; (void)n_in; (void)out_size;
    const float* x         = (const float*)d_in[0];
    const float* f_in_w    = (const float*)d_in[1];
    const float* f_conv_w  = (const float*)d_in[2];
    const float* f_conv_b  = (const float*)d_in[3];
    const float* f_xproj_w = (const float*)d_in[4];
    const float* f_dt_w    = (const float*)d_in[5];
    const float* f_dt_b    = (const float*)d_in[6];
    const float* f_A_log   = (const float*)d_in[7];
    const float* f_D       = (const float*)d_in[8];
    const float* f_out_w   = (const float*)d_in[9];
    const float* b_in_w    = (const float*)d_in[10];
    const float* b_conv_w  = (const float*)d_in[11];
    const float* b_conv_b  = (const float*)d_in[12];
    const float* b_xproj_w = (const float*)d_in[13];
    const float* b_dt_w    = (const float*)d_in[14];
    const float* b_dt_b    = (const float*)d_in[15];
    const float* b_A_log   = (const float*)d_in[16];
    const float* b_D       = (const float*)d_in[17];
    const float* b_out_w   = (const float*)d_in[18];
    float* out = (float*)d_out;

    cvt_split_all     <<<dim3(256, 4),    256>>>(f_in_w, b_in_w, f_out_w, b_out_w);
    gemm_in_tc        <<<dim3(8, 128, 2), 256>>>(x);
    conv_silu_kernel  <<<dim3(8, 8, 2),   512>>>(f_conv_w, f_conv_b, b_conv_w, b_conv_b);
    xproj_delta_kernel<<<dim3(128, 1, 2), 256>>>(f_xproj_w, b_xproj_w,
                                                 f_dt_w, f_dt_b, b_dt_w, b_dt_b);
    scan_kernel       <<<256, 128>>>(f_A_log, f_D, b_A_log, b_D);
    gemm_out_tc       <<<dim3(2, 128, 2), 256>>>(out);
}

// round 11
// speedup vs baseline: 1.0254x; 1.0254x over previous
#include <cuda_runtime.h>

// BiMamba: bidirectional mamba block.
//   x: (8, 256, 2048)  -> out: (8, 512, 2048)
// Big GEMMs (in-proj / out-proj) on tensor cores via split-bf16 (3-term) mma.
// R11 = R10 resubmit (R10 hit the periodic container failure; never executed):
//   xproj_delta vectorized-LDS rework + fast softplus; in_w split inlined
//   into gemm_in so scan lands in the profiled (4th) launch slot.
#define LSEQ   2048
#define DMODEL 256
#define DINNER 512
#define NST    16
#define NB     8
#define MROWS  (NB * LSEQ)   // 16384 rows per direction

// ---------------- scratch (device globals; no allocation allowed) -----------
__device__ float g_xi   [2u * MROWS * DINNER];  // K1 out (l-major) ; later yT (d-major)
__device__ float g_sz   [2u * MROWS * DINNER];  // silu(z)
__device__ float g_xc   [2u * MROWS * DINNER];  // conv output (silu'd)
__device__ float g_xdbl [2u * MROWS * 48];      // [unused(16) | B(16) | C(16)]
__device__ float g_delta[2u * MROWS * DINNER];  // softplus(dt @ dt_w^T + dt_b)

// split-bf16 out_w (hi/lo), k-major rows (in_w is split inline in gemm_in)
__device__ unsigned short g_woh[2][256 * 512];
__device__ unsigned short g_wol[2][256 * 512];

__device__ __forceinline__ float sigmoidf_(float v) {
    return __fdividef(1.0f, 1.0f + __expf(-v));
}

// hi = truncate-to-bf16 (exact residual), lo = rn-bf16 of residual
__device__ __forceinline__ void splitf_(float v, unsigned short& h, unsigned short& l) {
    unsigned u = __float_as_uint(v);
    unsigned hb = u & 0xFFFF0000u;
    h = (unsigned short)(hb >> 16);
    float r = v - __uint_as_float(hb);
    unsigned ur = __float_as_uint(r);
    l = (unsigned short)((ur + 0x7FFFu + ((ur >> 16) & 1u)) >> 16);
}

// split two values and pack as one k-pair word each (hi, lo)
__device__ __forceinline__ void pack2_(float a, float b, unsigned& hi, unsigned& lo) {
    unsigned short ha, la, hb, lb;
    splitf_(a, ha, la); splitf_(b, hb, lb);
    hi = (unsigned)ha | ((unsigned)hb << 16);
    lo = (unsigned)la | ((unsigned)lb << 16);
}

__device__ __forceinline__ void mma_bf16_(float* C, const unsigned* A, const unsigned* B) {
    asm volatile(
        "mma.sync.aligned.m16n8k16.row.col.f32.bf16.bf16.f32 "
        "{%0,%1,%2,%3},{%4,%5,%6,%7},{%8,%9},{%0,%1,%2,%3};\n"
        : "+f"(C[0]), "+f"(C[1]), "+f"(C[2]), "+f"(C[3])
        : "r"(A[0]), "r"(A[1]), "r"(A[2]), "r"(A[3]), "r"(B[0]), "r"(B[1]));
}

// ---------------- K1: in-projection (tensor core, inline weight split) ------
// C[m,e] = sum_k X[m,k] W[e,k]; X[m=(b,l),k] = x[b,k, l or L-1-l]
// e<512 -> g_xi ; e>=512 -> g_sz = silu(val)
__global__ __launch_bounds__(256) void gemm_in_tc(
    const float* __restrict__ x,
    const float* __restrict__ wf, const float* __restrict__ wb)
{
    const int dir = blockIdx.z;
    const int m0 = blockIdx.y * 128;
    const int n0 = blockIdx.x * 128;
    const int b  = m0 >> 11;
    const int l0 = m0 & (LSEQ - 1);
    const float* __restrict__ W = dir ? wb : wf;
    const float* __restrict__ xb = x + (size_t)b * DMODEL * LSEQ;

    // A pre-packed by k-pairs: Ahp[k2][m] = bf16(A[2k2][m]) | bf16(A[2k2+1][m])<<16
    __shared__ unsigned Ahp[16][136], Alp[16][136];
    __shared__ unsigned Bhp[128][20], Blp[128][20];   // [n][k2], 16 k2 + pad

    const int tid = threadIdx.x;
    const int warp = tid >> 5, lane = tid & 31;
    const int wm = (warp & 3) * 32, wn = (warp >> 2) * 64;
    const int grp = lane >> 2, qid = lane & 3;

    float c[2][8][4];
#pragma unroll
    for (int mi = 0; mi < 2; mi++)
#pragma unroll
        for (int ni = 0; ni < 8; ni++)
#pragma unroll
            for (int r = 0; r < 4; r++) c[mi][ni][r] = 0.f;

    const int ak2   = tid >> 4;          // 0..15
    const int amseg = (tid & 15) * 8;    // 0..120
    const int bnrow = tid >> 1;          // 0..127
    const int bkseg = (tid & 1) * 8;     // k2 offset 0 or 8

    for (int k0 = 0; k0 < DMODEL; k0 += 32) {
        // ---- A tile: fp32 -> split bf16, packed k-pairs ----
        const float* srcE = xb + (size_t)(k0 + 2 * ak2) * LSEQ;
        const float* srcO = srcE + LSEQ;
#pragma unroll
        for (int j = 0; j < 2; j++) {
            int mofs = amseg + j * 4;
            float4 ve, vo;
            if (dir == 0) {
                ve = *reinterpret_cast<const float4*>(srcE + l0 + mofs);
                vo = *reinterpret_cast<const float4*>(srcO + l0 + mofs);
            } else {
                float4 re = *reinterpret_cast<const float4*>(srcE + (LSEQ - 4) - (l0 + mofs));
                float4 ro = *reinterpret_cast<const float4*>(srcO + (LSEQ - 4) - (l0 + mofs));
                ve = make_float4(re.w, re.z, re.y, re.x);
                vo = make_float4(ro.w, ro.z, ro.y, ro.x);
            }
            unsigned short he[4], le[4], ho[4], lo_[4];
            splitf_(ve.x, he[0], le[0]); splitf_(ve.y, he[1], le[1]);
            splitf_(ve.z, he[2], le[2]); splitf_(ve.w, he[3], le[3]);
            splitf_(vo.x, ho[0], lo_[0]); splitf_(vo.y, ho[1], lo_[1]);
            splitf_(vo.z, ho[2], lo_[2]); splitf_(vo.w, ho[3], lo_[3]);
            uint4 ph, pl;
            ph.x = (unsigned)he[0] | ((unsigned)ho[0] << 16);
            ph.y = (unsigned)he[1] | ((unsigned)ho[1] << 16);
            ph.z = (unsigned)he[2] | ((unsigned)ho[2] << 16);
            ph.w = (unsigned)he[3] | ((unsigned)ho[3] << 16);
            pl.x = (unsigned)le[0] | ((unsigned)lo_[0] << 16);
            pl.y = (unsigned)le[1] | ((unsigned)lo_[1] << 16);
            pl.z = (unsigned)le[2] | ((unsigned)lo_[2] << 16);
            pl.w = (unsigned)le[3] | ((unsigned)lo_[3] << 16);
            *reinterpret_cast<uint4*>(&Ahp[ak2][mofs]) = ph;
            *reinterpret_cast<uint4*>(&Alp[ak2][mofs]) = pl;
        }
        // ---- B tile: fp32 weights -> split bf16 inline, k-pair packed ----
        {
            const float* wsrc = W + (size_t)(n0 + bnrow) * DMODEL + k0 + bkseg * 2;
            float4 w0 = *reinterpret_cast<const float4*>(wsrc);
            float4 w1 = *reinterpret_cast<const float4*>(wsrc + 4);
            float4 w2 = *reinterpret_cast<const float4*>(wsrc + 8);
            float4 w3 = *reinterpret_cast<const float4*>(wsrc + 12);
            unsigned bh[8], bl[8];
            pack2_(w0.x, w0.y, bh[0], bl[0]); pack2_(w0.z, w0.w, bh[1], bl[1]);
            pack2_(w1.x, w1.y, bh[2], bl[2]); pack2_(w1.z, w1.w, bh[3], bl[3]);
            pack2_(w2.x, w2.y, bh[4], bl[4]); pack2_(w2.z, w2.w, bh[5], bl[5]);
            pack2_(w3.x, w3.y, bh[6], bl[6]); pack2_(w3.z, w3.w, bh[7], bl[7]);
            *reinterpret_cast<uint4*>(&Bhp[bnrow][bkseg])     = make_uint4(bh[0], bh[1], bh[2], bh[3]);
            *reinterpret_cast<uint4*>(&Bhp[bnrow][bkseg + 4]) = make_uint4(bh[4], bh[5], bh[6], bh[7]);
            *reinterpret_cast<uint4*>(&Blp[bnrow][bkseg])     = make_uint4(bl[0], bl[1], bl[2], bl[3]);
            *reinterpret_cast<uint4*>(&Blp[bnrow][bkseg + 4]) = make_uint4(bl[4], bl[5], bl[6], bl[7]);
        }
        __syncthreads();
#pragma unroll
        for (int kk = 0; kk < 2; kk++) {             // two k16 chunks
            const int kq = kk * 8 + qid;             // k2 index of frag cols
            unsigned bh[8][2], bl[8][2];
#pragma unroll
            for (int ni = 0; ni < 8; ni++) {
                int n = wn + ni * 8 + grp;
                bh[ni][0] = Bhp[n][kq];     bh[ni][1] = Bhp[n][kq + 4];
                bl[ni][0] = Blp[n][kq];     bl[ni][1] = Blp[n][kq + 4];
            }
#pragma unroll
            for (int mi = 0; mi < 2; mi++) {
                int m = wm + mi * 16 + grp;
                unsigned ah[4], al[4];
                ah[0] = Ahp[kq][m];     ah[1] = Ahp[kq][m + 8];
                ah[2] = Ahp[kq + 4][m]; ah[3] = Ahp[kq + 4][m + 8];
                al[0] = Alp[kq][m];     al[1] = Alp[kq][m + 8];
                al[2] = Alp[kq + 4][m]; al[3] = Alp[kq + 4][m + 8];
#pragma unroll
                for (int ni = 0; ni < 8; ni++) mma_bf16_(c[mi][ni], ah, bh[ni]);
#pragma unroll
                for (int ni = 0; ni < 8; ni++) mma_bf16_(c[mi][ni], ah, bl[ni]);
#pragma unroll
                for (int ni = 0; ni < 8; ni++) mma_bf16_(c[mi][ni], al, bh[ni]);
            }
        }
        __syncthreads();
    }

    const size_t base = (size_t)dir * MROWS;
#pragma unroll
    for (int mi = 0; mi < 2; mi++) {
        int m = m0 + wm + mi * 16 + grp;
#pragma unroll
        for (int ni = 0; ni < 8; ni++) {
            int n = n0 + wn + ni * 8 + qid * 2;
            float v0 = c[mi][ni][0], v1 = c[mi][ni][1];
            float v2 = c[mi][ni][2], v3 = c[mi][ni][3];
            if (n < DINNER) {
                *reinterpret_cast<float2*>(&g_xi[(base + m) * DINNER + n]) = make_float2(v0, v1);
                *reinterpret_cast<float2*>(&g_xi[(base + m + 8) * DINNER + n]) = make_float2(v2, v3);
            } else {
                int e = n - DINNER;
                *reinterpret_cast<float2*>(&g_sz[(base + m) * DINNER + e]) =
                    make_float2(v0 * sigmoidf_(v0), v1 * sigmoidf_(v1));
                *reinterpret_cast<float2*>(&g_sz[(base + m + 8) * DINNER + e]) =
                    make_float2(v2 * sigmoidf_(v2), v3 * sigmoidf_(v3));
            }
        }
    }
}

// ---------------- K2: causal depthwise conv (k=4) + bias + silu -------------
__global__ __launch_bounds__(512) void conv_silu_kernel(
    const float* __restrict__ cwf, const float* __restrict__ cbf,
    const float* __restrict__ cwb, const float* __restrict__ cbb)
{
    const int dir = blockIdx.z;
    const int b   = blockIdx.y;
    const int l0  = blockIdx.x * 256;
    const int d   = threadIdx.x;
    const float* cw = dir ? cwb : cwf;
    const float* cb = dir ? cbb : cbf;
    const float w0 = cw[d * 4 + 0], w1 = cw[d * 4 + 1];
    const float w2 = cw[d * 4 + 2], w3 = cw[d * 4 + 3];
    const float bias = cb[d];

    const size_t rowbase = ((size_t)dir * MROWS + (size_t)b * LSEQ);
    const float* __restrict__ xip = g_xi + rowbase * DINNER + d;
    float* __restrict__ xcp = g_xc + rowbase * DINNER + d;

    float xm3 = (l0 >= 3) ? xip[(size_t)(l0 - 3) * DINNER] : 0.f;
    float xm2 = (l0 >= 2) ? xip[(size_t)(l0 - 2) * DINNER] : 0.f;
    float xm1 = (l0 >= 1) ? xip[(size_t)(l0 - 1) * DINNER] : 0.f;
    for (int ll = l0; ll < l0 + 256; ll++) {
        float xc = xip[(size_t)ll * DINNER];
        float v = fmaf(w0, xm3, fmaf(w1, xm2, fmaf(w2, xm1, fmaf(w3, xc, bias))));
        xcp[(size_t)ll * DINNER] = v * sigmoidf_(v);
        xm3 = xm2; xm2 = xm1; xm1 = xc;
    }
}

// ---------------- K3: fused x_proj GEMM + delta (vector-LDS rework) ---------
// Phase 1: x_dbl[m, 0..47] = xc @ xproj_w^T  (dt cols kept in smem, B/C -> gmem)
// Phase 2: delta[m, d] = softplus(dt @ dt_w^T + dt_b)
__global__ __launch_bounds__(256) void xproj_delta_kernel(
    const float* __restrict__ xwf, const float* __restrict__ xwb,
    const float* __restrict__ dtwf, const float* __restrict__ dtbf,
    const float* __restrict__ dtwb, const float* __restrict__ dtbb)
{
    const int dir = blockIdx.z;
    const float* __restrict__ W   = dir ? xwb : xwf;
    const float* __restrict__ dtw = dir ? dtwb : dtwf;
    const float* __restrict__ dtb = dir ? dtbb : dtbf;
    const int m0 = blockIdx.x * 128;

    __shared__ float sbuf[11264];        // 44 KB, phase-aliased
    float* As  = sbuf;                   // [16][132] kk-major = 2112 (phase 1)
    float* Bs  = sbuf + 2112;            // [16][49]  = 784           (phase 1)
    float* dtW = sbuf;                   // [512][17] = 8704          (phase 2)
    float* sB  = sbuf + 8704;            // [512]                     (phase 2)
    float* sdt = sbuf + 9216;            // [128][16] = 2048 (disjoint from phase 1)

    const int tid = threadIdx.x;
    const int ty = tid >> 4, tx = tid & 15;

    float acc[8][3];
#pragma unroll
    for (int i = 0; i < 8; i++)
#pragma unroll
        for (int j = 0; j < 3; j++) acc[i][j] = 0.f;

    const size_t abase = ((size_t)dir * MROWS + m0) * DINNER;
    for (int k0 = 0; k0 < DINNER; k0 += 16) {
#pragma unroll
        for (int j = 0; j < 8; j++) {
            int flat = tid + j * 256;
            int ml = flat >> 4, kk = flat & 15;
            As[kk * 132 + ml] = g_xc[abase + (size_t)ml * DINNER + (k0 + kk)];
        }
#pragma unroll
        for (int j = 0; j < 3; j++) {
            int flat = tid + j * 256;
            int e = flat >> 4, kk = flat & 15;
            Bs[kk * 49 + e] = W[(size_t)e * DINNER + (k0 + kk)];
        }
        __syncthreads();
#pragma unroll
        for (int kk = 0; kk < 16; kk++) {
            const float* arow = As + kk * 132 + ty * 8;
            float4 a0 = *reinterpret_cast<const float4*>(arow);
            float4 a1 = *reinterpret_cast<const float4*>(arow + 4);
            float av[8] = {a0.x, a0.y, a0.z, a0.w, a1.x, a1.y, a1.z, a1.w};
            float bv[3];
#pragma unroll
            for (int j = 0; j < 3; j++) bv[j] = Bs[kk * 49 + tx * 3 + j];
#pragma unroll
            for (int i = 0; i < 8; i++)
#pragma unroll
                for (int j = 0; j < 3; j++)
                    acc[i][j] = fmaf(av[i], bv[j], acc[i][j]);
        }
        __syncthreads();
    }

    // dt (cols 0..15) -> sdt ; B/C (cols 16..47) -> gmem
#pragma unroll
    for (int i = 0; i < 8; i++) {
#pragma unroll
        for (int j = 0; j < 3; j++) {
            int col = tx * 3 + j;
            if (col < 16)
                sdt[(ty * 8 + i) * 16 + col] = acc[i][j];
            else
                g_xdbl[((size_t)dir * MROWS + m0 + ty * 8 + i) * 48 + col] = acc[i][j];
        }
    }
    // load dt_w (padded 17) + bias; overwrites As/Bs (all reads done)
#pragma unroll
    for (int i = 0; i < 32; i++) {
        int flat = tid + i * 256;            // 8192 = 512*16
        dtW[(flat >> 4) * 17 + (flat & 15)] = dtw[flat];
    }
#pragma unroll
    for (int i = 0; i < 2; i++) sB[tid + i * 256] = dtb[tid + i * 256];
    __syncthreads();

    // phase 2: dt_w rows register-resident, sdt rows via broadcast LDS.128
    const int d = tid & 255;
    float w0r[16], w1r[16];
#pragma unroll
    for (int r = 0; r < 16; r++) {
        w0r[r] = dtW[d * 17 + r];
        w1r[r] = dtW[(d + 256) * 17 + r];
    }
    const float b0 = sB[d], b1 = sB[d + 256];
    float* __restrict__ outp = g_delta + ((size_t)dir * MROWS + m0) * DINNER;
#pragma unroll 2
    for (int ml = 0; ml < 128; ml++) {
        const float* dtrow = sdt + ml * 16;
        float4 t0 = *reinterpret_cast<const float4*>(dtrow);
        float4 t1 = *reinterpret_cast<const float4*>(dtrow + 4);
        float4 t2 = *reinterpret_cast<const float4*>(dtrow + 8);
        float4 t3 = *reinterpret_cast<const float4*>(dtrow + 12);
        float dtr[16] = {t0.x, t0.y, t0.z, t0.w, t1.x, t1.y, t1.z, t1.w,
                         t2.x, t2.y, t2.z, t2.w, t3.x, t3.y, t3.z, t3.w};
        float a0 = b0, a1 = b1;
#pragma unroll
        for (int r = 0; r < 16; r++) {
            a0 = fmaf(dtr[r], w0r[r], a0);
            a1 = fmaf(dtr[r], w1r[r], a1);
        }
        float sp0 = (a0 > 15.f) ? a0 : __logf(1.f + __expf(a0));
        float sp1 = (a1 > 15.f) ? a1 : __logf(1.f + __expf(a1));
        outp[(size_t)ml * DINNER + d]       = sp0;
        outp[(size_t)ml * DINNER + d + 256] = sp1;
    }
}

// ---------------- K4: selective scan (profiled slot) ------------------------
// 4 threads per (dir,b,d) channel, 4 states each; B/C chunk-staged in smem.
// Writes yT (aliased onto g_xi) in d-major layout.
__global__ __launch_bounds__(128) void scan_kernel(
    const float* __restrict__ Alf, const float* __restrict__ Df,
    const float* __restrict__ Alb, const float* __restrict__ Db)
{
    const int bi   = blockIdx.x;         // 256 blocks: dir(2) x b(8) x dblk(16)
    const int dir  = bi >> 7;
    const int b    = (bi >> 4) & 7;
    const int dblk = bi & 15;
    const int tid  = threadIdx.x;
    const int w    = tid >> 5;
    const int lane = tid & 31;
    const int q    = lane >> 3;
    const int dlo  = lane & 7;
    const int d    = dblk * 32 + w * 8 + dlo;

    const float* Al = dir ? Alb : Alf;
    const float* Dp = dir ? Db : Df;

    float A[4];
#pragma unroll
    for (int n = 0; n < 4; n++) A[n] = -__expf(Al[d * NST + q * 4 + n]);
    const float Dd = Dp[d];

    float h[4];
#pragma unroll
    for (int n = 0; n < 4; n++) h[n] = 0.f;

    const size_t mb = (size_t)dir * MROWS + (size_t)b * LSEQ;
    const float* __restrict__ dl  = g_delta + mb * DINNER + d;
    const float* __restrict__ xp  = g_xc    + mb * DINNER + d;
    const float* __restrict__ szp = g_sz    + mb * DINNER + d;
    float* __restrict__ yTp = g_xi + ((size_t)(dir * DINNER + d) * NB + b) * LSEQ;
    const float* __restrict__ bc  = g_xdbl  + mb * 48 + 16;

    __shared__ float sBC[64][32];

    float dcur = dl[0], xcur = xp[0], szcur = szp[0];
    float yb4[4];

    for (int t0 = 0; t0 < LSEQ; t0 += 64) {
        __syncthreads();
#pragma unroll
        for (int i = 0; i < 16; i++) {
            int flat = tid + i * 128;
            int tt = flat >> 5, j = flat & 31;
            sBC[tt][j] = bc[(size_t)(t0 + tt) * 48 + j];
        }
        __syncthreads();
#pragma unroll 4
        for (int t = 0; t < 64; t++) {
            const int tg = t0 + t;
            const int tn = (tg + 1 < LSEQ) ? (tg + 1) : tg;
            float dn  = dl[(size_t)tn * DINNER];
            float xn  = xp[(size_t)tn * DINNER];
            float szn = szp[(size_t)tn * DINNER];

            float4 Bv = *reinterpret_cast<const float4*>(&sBC[t][q * 4]);
            float4 Cv = *reinterpret_cast<const float4*>(&sBC[t][16 + q * 4]);

            const float dx = dcur * xcur;
            float y;
            h[0] = fmaf(__expf(dcur * A[0]), h[0], dx * Bv.x); y = h[0] * Cv.x;
            h[1] = fmaf(__expf(dcur * A[1]), h[1], dx * Bv.y); y = fmaf(h[1], Cv.y, y);
            h[2] = fmaf(__expf(dcur * A[2]), h[2], dx * Bv.z); y = fmaf(h[2], Cv.z, y);
            h[3] = fmaf(__expf(dcur * A[3]), h[3], dx * Bv.w); y = fmaf(h[3], Cv.w, y);

            y += __shfl_xor_sync(0xFFFFFFFFu, y, 8);
            y += __shfl_xor_sync(0xFFFFFFFFu, y, 16);

            yb4[t & 3] = (y + xcur * Dd) * szcur;
            if ((t & 3) == 3 && q == 0) {
                *reinterpret_cast<float4*>(&yTp[tg - 3]) =
                    make_float4(yb4[0], yb4[1], yb4[2], yb4[3]);
            }
            dcur = dn; xcur = xn; szcur = szn;
        }
    }
}

// ---------------- K5: out_w split prepass -----------------------------------
__global__ __launch_bounds__(256) void cvt_split_out(
    const float* __restrict__ fout, const float* __restrict__ bout)
{
    const int which = blockIdx.y;
    const float* __restrict__ src = which ? bout : fout;
    unsigned short* hi = g_woh[which];
    unsigned short* lo = g_wol[which];

    int i = blockIdx.x * 256 + threadIdx.x;   // 32768 float4s
    float4 v = reinterpret_cast<const float4*>(src)[i];
    unsigned short h0, h1, h2, h3, q0, q1, q2, q3;
    splitf_(v.x, h0, q0); splitf_(v.y, h1, q1);
    splitf_(v.z, h2, q2); splitf_(v.w, h3, q3);
    reinterpret_cast<uint2*>(hi)[i] =
        make_uint2((unsigned)h0 | ((unsigned)h1 << 16), (unsigned)h2 | ((unsigned)h3 << 16));
    reinterpret_cast<uint2*>(lo)[i] =
        make_uint2((unsigned)q0 | ((unsigned)q1 << 16), (unsigned)q2 | ((unsigned)q3 << 16));
}

// ---------------- K6: out-projection (tensor core) + un-flip + concat -------
// out[b, dir*256+o, l_phys] = sum_d yT[d, b, l] * W[o, d]
__global__ __launch_bounds__(256) void gemm_out_tc(float* __restrict__ out)
{
    const int dir = blockIdx.z;
    const int m0 = blockIdx.y * 128;
    const int n0 = blockIdx.x * 128;
    const int b  = m0 >> 11;
    const int l0 = m0 & (LSEQ - 1);
    const unsigned short* __restrict__ Wh = g_woh[dir];
    const unsigned short* __restrict__ Wl = g_wol[dir];

    __shared__ unsigned Ahp[16][136], Alp[16][136];
    __shared__ unsigned Bhp[128][20], Blp[128][20];

    const int tid = threadIdx.x;
    const int warp = tid >> 5, lane = tid & 31;
    const int wm = (warp & 3) * 32, wn = (warp >> 2) * 64;
    const int grp = lane >> 2, qid = lane & 3;

    float c[2][8][4];
#pragma unroll
    for (int mi = 0; mi < 2; mi++)
#pragma unroll
        for (int ni = 0; ni < 8; ni++)
#pragma unroll
            for (int r = 0; r < 4; r++) c[mi][ni][r] = 0.f;

    const int ak2   = tid >> 4;
    const int amseg = (tid & 15) * 8;
    const int bnrow = tid >> 1;
    const int bkseg = (tid & 1) * 8;

    for (int k0 = 0; k0 < DINNER; k0 += 32) {
        const float* srcE = g_xi +
            ((size_t)(dir * DINNER + k0 + 2 * ak2) * NB + b) * LSEQ + l0;
        const float* srcO = srcE + (size_t)NB * LSEQ;
#pragma unroll
        for (int j = 0; j < 2; j++) {
            int mofs = amseg + j * 4;
            float4 ve = *reinterpret_cast<const float4*>(srcE + mofs);
            float4 vo = *reinterpret_cast<const float4*>(srcO + mofs);
            unsigned short he[4], le[4], ho[4], lo_[4];
            splitf_(ve.x, he[0], le[0]); splitf_(ve.y, he[1], le[1]);
            splitf_(ve.z, he[2], le[2]); splitf_(ve.w, he[3], le[3]);
            splitf_(vo.x, ho[0], lo_[0]); splitf_(vo.y, ho[1], lo_[1]);
            splitf_(vo.z, ho[2], lo_[2]); splitf_(vo.w, ho[3], lo_[3]);
            uint4 ph, pl;
            ph.x = (unsigned)he[0] | ((unsigned)ho[0] << 16);
            ph.y = (unsigned)he[1] | ((unsigned)ho[1] << 16);
            ph.z = (unsigned)he[2] | ((unsigned)ho[2] << 16);
            ph.w = (unsigned)he[3] | ((unsigned)ho[3] << 16);
            pl.x = (unsigned)le[0] | ((unsigned)lo_[0] << 16);
            pl.y = (unsigned)le[1] | ((unsigned)lo_[1] << 16);
            pl.z = (unsigned)le[2] | ((unsigned)lo_[2] << 16);
            pl.w = (unsigned)le[3] | ((unsigned)lo_[3] << 16);
            *reinterpret_cast<uint4*>(&Ahp[ak2][mofs]) = ph;
            *reinterpret_cast<uint4*>(&Alp[ak2][mofs]) = pl;
        }
        {
            const unsigned short* wh = Wh + (size_t)(n0 + bnrow) * DINNER + k0 + bkseg * 2;
            const unsigned short* wl = Wl + (size_t)(n0 + bnrow) * DINNER + k0 + bkseg * 2;
            *reinterpret_cast<uint4*>(&Bhp[bnrow][bkseg]) = *reinterpret_cast<const uint4*>(wh);
            *reinterpret_cast<uint4*>(&Bhp[bnrow][bkseg + 4]) = *reinterpret_cast<const uint4*>(wh + 8);
            *reinterpret_cast<uint4*>(&Blp[bnrow][bkseg]) = *reinterpret_cast<const uint4*>(wl);
            *reinterpret_cast<uint4*>(&Blp[bnrow][bkseg + 4]) = *reinterpret_cast<const uint4*>(wl + 8);
        }
        __syncthreads();
#pragma unroll
        for (int kk = 0; kk < 2; kk++) {
            const int kq = kk * 8 + qid;
            unsigned bh[8][2], bl[8][2];
#pragma unroll
            for (int ni = 0; ni < 8; ni++) {
                int n = wn + ni * 8 + grp;
                bh[ni][0] = Bhp[n][kq];     bh[ni][1] = Bhp[n][kq + 4];
                bl[ni][0] = Blp[n][kq];     bl[ni][1] = Blp[n][kq + 4];
            }
#pragma unroll
            for (int mi = 0; mi < 2; mi++) {
                int m = wm + mi * 16 + grp;
                unsigned ah[4], al[4];
                ah[0] = Ahp[kq][m];     ah[1] = Ahp[kq][m + 8];
                ah[2] = Ahp[kq + 4][m]; ah[3] = Ahp[kq + 4][m + 8];
                al[0] = Alp[kq][m];     al[1] = Alp[kq][m + 8];
                al[2] = Alp[kq + 4][m]; al[3] = Alp[kq + 4][m + 8];
#pragma unroll
                for (int ni = 0; ni < 8; ni++) mma_bf16_(c[mi][ni], ah, bh[ni]);
#pragma unroll
                for (int ni = 0; ni < 8; ni++) mma_bf16_(c[mi][ni], ah, bl[ni]);
#pragma unroll
                for (int ni = 0; ni < 8; ni++) mma_bf16_(c[mi][ni], al, bh[ni]);
            }
        }
        __syncthreads();
    }

#pragma unroll
    for (int mi = 0; mi < 2; mi++) {
        int l = l0 + wm + mi * 16 + grp;
        int lp0 = dir ? (LSEQ - 1 - l) : l;
        int lp1 = dir ? (LSEQ - 1 - (l + 8)) : (l + 8);
#pragma unroll
        for (int ni = 0; ni < 8; ni++) {
            int o = n0 + wn + ni * 8 + qid * 2;
            float* op0 = out + ((size_t)b * (2 * DMODEL) + dir * DMODEL + o) * LSEQ;
            float* op1 = op0 + LSEQ;
            op0[lp0] = c[mi][ni][0];
            op1[lp0] = c[mi][ni][1];
            op0[lp1] = c[mi][ni][2];
            op1[lp1] = c[mi][ni][3];
        }
    }
}

// ---------------- launch -----------------------------------------------------
extern "C" void kernel_launch(void* const* d_in, const int* in_sizes, int n_in,
                              void* d_out, int out_size)
{
    (void)in_sizes; (void)n_in; (void)out_size;
    const float* x         = (const float*)d_in[0];
    const float* f_in_w    = (const float*)d_in[1];
    const float* f_conv_w  = (const float*)d_in[2];
    const float* f_conv_b  = (const float*)d_in[3];
    const float* f_xproj_w = (const float*)d_in[4];
    const float* f_dt_w    = (const float*)d_in[5];
    const float* f_dt_b    = (const float*)d_in[6];
    const float* f_A_log   = (const float*)d_in[7];
    const float* f_D       = (const float*)d_in[8];
    const float* f_out_w   = (const float*)d_in[9];
    const float* b_in_w    = (const float*)d_in[10];
    const float* b_conv_w  = (const float*)d_in[11];
    const float* b_conv_b  = (const float*)d_in[12];
    const float* b_xproj_w = (const float*)d_in[13];
    const float* b_dt_w    = (const float*)d_in[14];
    const float* b_dt_b    = (const float*)d_in[15];
    const float* b_A_log   = (const float*)d_in[16];
    const float* b_D       = (const float*)d_in[17];
    const float* b_out_w   = (const float*)d_in[18];
    float* out = (float*)d_out;

    gemm_in_tc        <<<dim3(8, 128, 2), 256>>>(x, f_in_w, b_in_w);
    conv_silu_kernel  <<<dim3(8, 8, 2),   512>>>(f_conv_w, f_conv_b, b_conv_w, b_conv_b);
    xproj_delta_kernel<<<dim3(128, 1, 2), 256>>>(f_xproj_w, b_xproj_w,
                                                 f_dt_w, f_dt_b, b_dt_w, b_dt_b);
    scan_kernel       <<<256, 128>>>(f_A_log, f_D, b_A_log, b_D);   // profiled slot 4
    cvt_split_out     <<<dim3(128, 2),    256>>>(f_out_w, b_out_w);
    gemm_out_tc       <<<dim3(2, 128, 2), 256>>>(out);
}

// round 12
// speedup vs baseline: 1.5361x; 1.4980x over previous
#include <cuda_runtime.h>

// BiMamba: bidirectional mamba block.
//   x: (8, 256, 2048)  -> out: (8, 512, 2048)
// Big GEMMs (in-proj / out-proj) on tensor cores via split-bf16 (3-term) mma.
// R12 = R11 + scan_kernel rewritten with full smem staging (scan was 721us,
//       57% of total, pure gmem-latency-bound at 600 cyc/step).
#define LSEQ   2048
#define DMODEL 256
#define DINNER 512
#define NST    16
#define NB     8
#define MROWS  (NB * LSEQ)   // 16384 rows per direction

// ---------------- scratch (device globals; no allocation allowed) -----------
__device__ float g_xi   [2u * MROWS * DINNER];  // K1 out (l-major) ; later yT (d-major)
__device__ float g_sz   [2u * MROWS * DINNER];  // silu(z)
__device__ float g_xc   [2u * MROWS * DINNER];  // conv output (silu'd)
__device__ float g_xdbl [2u * MROWS * 48];      // [unused(16) | B(16) | C(16)]
__device__ float g_delta[2u * MROWS * DINNER];  // softplus(dt @ dt_w^T + dt_b)

// split-bf16 out_w (hi/lo), k-major rows (in_w is split inline in gemm_in)
__device__ unsigned short g_woh[2][256 * 512];
__device__ unsigned short g_wol[2][256 * 512];

__device__ __forceinline__ float sigmoidf_(float v) {
    return __fdividef(1.0f, 1.0f + __expf(-v));
}

// hi = truncate-to-bf16 (exact residual), lo = rn-bf16 of residual
__device__ __forceinline__ void splitf_(float v, unsigned short& h, unsigned short& l) {
    unsigned u = __float_as_uint(v);
    unsigned hb = u & 0xFFFF0000u;
    h = (unsigned short)(hb >> 16);
    float r = v - __uint_as_float(hb);
    unsigned ur = __float_as_uint(r);
    l = (unsigned short)((ur + 0x7FFFu + ((ur >> 16) & 1u)) >> 16);
}

// split two values and pack as one k-pair word each (hi, lo)
__device__ __forceinline__ void pack2_(float a, float b, unsigned& hi, unsigned& lo) {
    unsigned short ha, la, hb, lb;
    splitf_(a, ha, la); splitf_(b, hb, lb);
    hi = (unsigned)ha | ((unsigned)hb << 16);
    lo = (unsigned)la | ((unsigned)lb << 16);
}

__device__ __forceinline__ void mma_bf16_(float* C, const unsigned* A, const unsigned* B) {
    asm volatile(
        "mma.sync.aligned.m16n8k16.row.col.f32.bf16.bf16.f32 "
        "{%0,%1,%2,%3},{%4,%5,%6,%7},{%8,%9},{%0,%1,%2,%3};\n"
        : "+f"(C[0]), "+f"(C[1]), "+f"(C[2]), "+f"(C[3])
        : "r"(A[0]), "r"(A[1]), "r"(A[2]), "r"(A[3]), "r"(B[0]), "r"(B[1]));
}

// ---------------- K1: in-projection (tensor core, inline weight split) ------
// C[m,e] = sum_k X[m,k] W[e,k]; X[m=(b,l),k] = x[b,k, l or L-1-l]
// e<512 -> g_xi ; e>=512 -> g_sz = silu(val)
__global__ __launch_bounds__(256) void gemm_in_tc(
    const float* __restrict__ x,
    const float* __restrict__ wf, const float* __restrict__ wb)
{
    const int dir = blockIdx.z;
    const int m0 = blockIdx.y * 128;
    const int n0 = blockIdx.x * 128;
    const int b  = m0 >> 11;
    const int l0 = m0 & (LSEQ - 1);
    const float* __restrict__ W = dir ? wb : wf;
    const float* __restrict__ xb = x + (size_t)b * DMODEL * LSEQ;

    __shared__ unsigned Ahp[16][136], Alp[16][136];
    __shared__ unsigned Bhp[128][20], Blp[128][20];   // [n][k2], 16 k2 + pad

    const int tid = threadIdx.x;
    const int warp = tid >> 5, lane = tid & 31;
    const int wm = (warp & 3) * 32, wn = (warp >> 2) * 64;
    const int grp = lane >> 2, qid = lane & 3;

    float c[2][8][4];
#pragma unroll
    for (int mi = 0; mi < 2; mi++)
#pragma unroll
        for (int ni = 0; ni < 8; ni++)
#pragma unroll
            for (int r = 0; r < 4; r++) c[mi][ni][r] = 0.f;

    const int ak2   = tid >> 4;          // 0..15
    const int amseg = (tid & 15) * 8;    // 0..120
    const int bnrow = tid >> 1;          // 0..127
    const int bkseg = (tid & 1) * 8;     // k2 offset 0 or 8

    for (int k0 = 0; k0 < DMODEL; k0 += 32) {
        // ---- A tile: fp32 -> split bf16, packed k-pairs ----
        const float* srcE = xb + (size_t)(k0 + 2 * ak2) * LSEQ;
        const float* srcO = srcE + LSEQ;
#pragma unroll
        for (int j = 0; j < 2; j++) {
            int mofs = amseg + j * 4;
            float4 ve, vo;
            if (dir == 0) {
                ve = *reinterpret_cast<const float4*>(srcE + l0 + mofs);
                vo = *reinterpret_cast<const float4*>(srcO + l0 + mofs);
            } else {
                float4 re = *reinterpret_cast<const float4*>(srcE + (LSEQ - 4) - (l0 + mofs));
                float4 ro = *reinterpret_cast<const float4*>(srcO + (LSEQ - 4) - (l0 + mofs));
                ve = make_float4(re.w, re.z, re.y, re.x);
                vo = make_float4(ro.w, ro.z, ro.y, ro.x);
            }
            unsigned short he[4], le[4], ho[4], lo_[4];
            splitf_(ve.x, he[0], le[0]); splitf_(ve.y, he[1], le[1]);
            splitf_(ve.z, he[2], le[2]); splitf_(ve.w, he[3], le[3]);
            splitf_(vo.x, ho[0], lo_[0]); splitf_(vo.y, ho[1], lo_[1]);
            splitf_(vo.z, ho[2], lo_[2]); splitf_(vo.w, ho[3], lo_[3]);
            uint4 ph, pl;
            ph.x = (unsigned)he[0] | ((unsigned)ho[0] << 16);
            ph.y = (unsigned)he[1] | ((unsigned)ho[1] << 16);
            ph.z = (unsigned)he[2] | ((unsigned)ho[2] << 16);
            ph.w = (unsigned)he[3] | ((unsigned)ho[3] << 16);
            pl.x = (unsigned)le[0] | ((unsigned)lo_[0] << 16);
            pl.y = (unsigned)le[1] | ((unsigned)lo_[1] << 16);
            pl.z = (unsigned)le[2] | ((unsigned)lo_[2] << 16);
            pl.w = (unsigned)le[3] | ((unsigned)lo_[3] << 16);
            *reinterpret_cast<uint4*>(&Ahp[ak2][mofs]) = ph;
            *reinterpret_cast<uint4*>(&Alp[ak2][mofs]) = pl;
        }
        // ---- B tile: fp32 weights -> split bf16 inline, k-pair packed ----
        {
            const float* wsrc = W + (size_t)(n0 + bnrow) * DMODEL + k0 + bkseg * 2;
            float4 w0 = *reinterpret_cast<const float4*>(wsrc);
            float4 w1 = *reinterpret_cast<const float4*>(wsrc + 4);
            float4 w2 = *reinterpret_cast<const float4*>(wsrc + 8);
            float4 w3 = *reinterpret_cast<const float4*>(wsrc + 12);
            unsigned bh[8], bl[8];
            pack2_(w0.x, w0.y, bh[0], bl[0]); pack2_(w0.z, w0.w, bh[1], bl[1]);
            pack2_(w1.x, w1.y, bh[2], bl[2]); pack2_(w1.z, w1.w, bh[3], bl[3]);
            pack2_(w2.x, w2.y, bh[4], bl[4]); pack2_(w2.z, w2.w, bh[5], bl[5]);
            pack2_(w3.x, w3.y, bh[6], bl[6]); pack2_(w3.z, w3.w, bh[7], bl[7]);
            *reinterpret_cast<uint4*>(&Bhp[bnrow][bkseg])     = make_uint4(bh[0], bh[1], bh[2], bh[3]);
            *reinterpret_cast<uint4*>(&Bhp[bnrow][bkseg + 4]) = make_uint4(bh[4], bh[5], bh[6], bh[7]);
            *reinterpret_cast<uint4*>(&Blp[bnrow][bkseg])     = make_uint4(bl[0], bl[1], bl[2], bl[3]);
            *reinterpret_cast<uint4*>(&Blp[bnrow][bkseg + 4]) = make_uint4(bl[4], bl[5], bl[6], bl[7]);
        }
        __syncthreads();
#pragma unroll
        for (int kk = 0; kk < 2; kk++) {             // two k16 chunks
            const int kq = kk * 8 + qid;             // k2 index of frag cols
            unsigned bh[8][2], bl[8][2];
#pragma unroll
            for (int ni = 0; ni < 8; ni++) {
                int n = wn + ni * 8 + grp;
                bh[ni][0] = Bhp[n][kq];     bh[ni][1] = Bhp[n][kq + 4];
                bl[ni][0] = Blp[n][kq];     bl[ni][1] = Blp[n][kq + 4];
            }
#pragma unroll
            for (int mi = 0; mi < 2; mi++) {
                int m = wm + mi * 16 + grp;
                unsigned ah[4], al[4];
                ah[0] = Ahp[kq][m];     ah[1] = Ahp[kq][m + 8];
                ah[2] = Ahp[kq + 4][m]; ah[3] = Ahp[kq + 4][m + 8];
                al[0] = Alp[kq][m];     al[1] = Alp[kq][m + 8];
                al[2] = Alp[kq + 4][m]; al[3] = Alp[kq + 4][m + 8];
#pragma unroll
                for (int ni = 0; ni < 8; ni++) mma_bf16_(c[mi][ni], ah, bh[ni]);
#pragma unroll
                for (int ni = 0; ni < 8; ni++) mma_bf16_(c[mi][ni], ah, bl[ni]);
#pragma unroll
                for (int ni = 0; ni < 8; ni++) mma_bf16_(c[mi][ni], al, bh[ni]);
            }
        }
        __syncthreads();
    }

    const size_t base = (size_t)dir * MROWS;
#pragma unroll
    for (int mi = 0; mi < 2; mi++) {
        int m = m0 + wm + mi * 16 + grp;
#pragma unroll
        for (int ni = 0; ni < 8; ni++) {
            int n = n0 + wn + ni * 8 + qid * 2;
            float v0 = c[mi][ni][0], v1 = c[mi][ni][1];
            float v2 = c[mi][ni][2], v3 = c[mi][ni][3];
            if (n < DINNER) {
                *reinterpret_cast<float2*>(&g_xi[(base + m) * DINNER + n]) = make_float2(v0, v1);
                *reinterpret_cast<float2*>(&g_xi[(base + m + 8) * DINNER + n]) = make_float2(v2, v3);
            } else {
                int e = n - DINNER;
                *reinterpret_cast<float2*>(&g_sz[(base + m) * DINNER + e]) =
                    make_float2(v0 * sigmoidf_(v0), v1 * sigmoidf_(v1));
                *reinterpret_cast<float2*>(&g_sz[(base + m + 8) * DINNER + e]) =
                    make_float2(v2 * sigmoidf_(v2), v3 * sigmoidf_(v3));
            }
        }
    }
}

// ---------------- K2: causal depthwise conv (k=4) + bias + silu -------------
__global__ __launch_bounds__(512) void conv_silu_kernel(
    const float* __restrict__ cwf, const float* __restrict__ cbf,
    const float* __restrict__ cwb, const float* __restrict__ cbb)
{
    const int dir = blockIdx.z;
    const int b   = blockIdx.y;
    const int l0  = blockIdx.x * 256;
    const int d   = threadIdx.x;
    const float* cw = dir ? cwb : cwf;
    const float* cb = dir ? cbb : cbf;
    const float w0 = cw[d * 4 + 0], w1 = cw[d * 4 + 1];
    const float w2 = cw[d * 4 + 2], w3 = cw[d * 4 + 3];
    const float bias = cb[d];

    const size_t rowbase = ((size_t)dir * MROWS + (size_t)b * LSEQ);
    const float* __restrict__ xip = g_xi + rowbase * DINNER + d;
    float* __restrict__ xcp = g_xc + rowbase * DINNER + d;

    float xm3 = (l0 >= 3) ? xip[(size_t)(l0 - 3) * DINNER] : 0.f;
    float xm2 = (l0 >= 2) ? xip[(size_t)(l0 - 2) * DINNER] : 0.f;
    float xm1 = (l0 >= 1) ? xip[(size_t)(l0 - 1) * DINNER] : 0.f;
    for (int ll = l0; ll < l0 + 256; ll++) {
        float xc = xip[(size_t)ll * DINNER];
        float v = fmaf(w0, xm3, fmaf(w1, xm2, fmaf(w2, xm1, fmaf(w3, xc, bias))));
        xcp[(size_t)ll * DINNER] = v * sigmoidf_(v);
        xm3 = xm2; xm2 = xm1; xm1 = xc;
    }
}

// ---------------- K3: fused x_proj GEMM + delta (vector-LDS rework) ---------
__global__ __launch_bounds__(256) void xproj_delta_kernel(
    const float* __restrict__ xwf, const float* __restrict__ xwb,
    const float* __restrict__ dtwf, const float* __restrict__ dtbf,
    const float* __restrict__ dtwb, const float* __restrict__ dtbb)
{
    const int dir = blockIdx.z;
    const float* __restrict__ W   = dir ? xwb : xwf;
    const float* __restrict__ dtw = dir ? dtwb : dtwf;
    const float* __restrict__ dtb = dir ? dtbb : dtbf;
    const int m0 = blockIdx.x * 128;

    __shared__ float sbuf[11264];        // 44 KB, phase-aliased
    float* As  = sbuf;                   // [16][132] kk-major = 2112 (phase 1)
    float* Bs  = sbuf + 2112;            // [16][49]  = 784           (phase 1)
    float* dtW = sbuf;                   // [512][17] = 8704          (phase 2)
    float* sB  = sbuf + 8704;            // [512]                     (phase 2)
    float* sdt = sbuf + 9216;            // [128][16] = 2048 (disjoint from phase 1)

    const int tid = threadIdx.x;
    const int ty = tid >> 4, tx = tid & 15;

    float acc[8][3];
#pragma unroll
    for (int i = 0; i < 8; i++)
#pragma unroll
        for (int j = 0; j < 3; j++) acc[i][j] = 0.f;

    const size_t abase = ((size_t)dir * MROWS + m0) * DINNER;
    for (int k0 = 0; k0 < DINNER; k0 += 16) {
#pragma unroll
        for (int j = 0; j < 8; j++) {
            int flat = tid + j * 256;
            int ml = flat >> 4, kk = flat & 15;
            As[kk * 132 + ml] = g_xc[abase + (size_t)ml * DINNER + (k0 + kk)];
        }
#pragma unroll
        for (int j = 0; j < 3; j++) {
            int flat = tid + j * 256;
            int e = flat >> 4, kk = flat & 15;
            Bs[kk * 49 + e] = W[(size_t)e * DINNER + (k0 + kk)];
        }
        __syncthreads();
#pragma unroll
        for (int kk = 0; kk < 16; kk++) {
            const float* arow = As + kk * 132 + ty * 8;
            float4 a0 = *reinterpret_cast<const float4*>(arow);
            float4 a1 = *reinterpret_cast<const float4*>(arow + 4);
            float av[8] = {a0.x, a0.y, a0.z, a0.w, a1.x, a1.y, a1.z, a1.w};
            float bv[3];
#pragma unroll
            for (int j = 0; j < 3; j++) bv[j] = Bs[kk * 49 + tx * 3 + j];
#pragma unroll
            for (int i = 0; i < 8; i++)
#pragma unroll
                for (int j = 0; j < 3; j++)
                    acc[i][j] = fmaf(av[i], bv[j], acc[i][j]);
        }
        __syncthreads();
    }

    // dt (cols 0..15) -> sdt ; B/C (cols 16..47) -> gmem
#pragma unroll
    for (int i = 0; i < 8; i++) {
#pragma unroll
        for (int j = 0; j < 3; j++) {
            int col = tx * 3 + j;
            if (col < 16)
                sdt[(ty * 8 + i) * 16 + col] = acc[i][j];
            else
                g_xdbl[((size_t)dir * MROWS + m0 + ty * 8 + i) * 48 + col] = acc[i][j];
        }
    }
    // load dt_w (padded 17) + bias; overwrites As/Bs (all reads done)
#pragma unroll
    for (int i = 0; i < 32; i++) {
        int flat = tid + i * 256;            // 8192 = 512*16
        dtW[(flat >> 4) * 17 + (flat & 15)] = dtw[flat];
    }
#pragma unroll
    for (int i = 0; i < 2; i++) sB[tid + i * 256] = dtb[tid + i * 256];
    __syncthreads();

    // phase 2: dt_w rows register-resident, sdt rows via broadcast LDS.128
    const int d = tid & 255;
    float w0r[16], w1r[16];
#pragma unroll
    for (int r = 0; r < 16; r++) {
        w0r[r] = dtW[d * 17 + r];
        w1r[r] = dtW[(d + 256) * 17 + r];
    }
    const float b0 = sB[d], b1 = sB[d + 256];
    float* __restrict__ outp = g_delta + ((size_t)dir * MROWS + m0) * DINNER;
#pragma unroll 2
    for (int ml = 0; ml < 128; ml++) {
        const float* dtrow = sdt + ml * 16;
        float4 t0 = *reinterpret_cast<const float4*>(dtrow);
        float4 t1 = *reinterpret_cast<const float4*>(dtrow + 4);
        float4 t2 = *reinterpret_cast<const float4*>(dtrow + 8);
        float4 t3 = *reinterpret_cast<const float4*>(dtrow + 12);
        float dtr[16] = {t0.x, t0.y, t0.z, t0.w, t1.x, t1.y, t1.z, t1.w,
                         t2.x, t2.y, t2.z, t2.w, t3.x, t3.y, t3.z, t3.w};
        float a0 = b0, a1 = b1;
#pragma unroll
        for (int r = 0; r < 16; r++) {
            a0 = fmaf(dtr[r], w0r[r], a0);
            a1 = fmaf(dtr[r], w1r[r], a1);
        }
        float sp0 = (a0 > 15.f) ? a0 : __logf(1.f + __expf(a0));
        float sp1 = (a1 > 15.f) ? a1 : __logf(1.f + __expf(a1));
        outp[(size_t)ml * DINNER + d]       = sp0;
        outp[(size_t)ml * DINNER + d + 256] = sp1;
    }
}

// ---------------- K4: selective scan (full smem staging) --------------------
// 4 threads per (dir,b,d) channel, 4 states each.
// delta/xc/sz staged per 64-step chunk via coalesced cooperative loads;
// y staged in smem and stored per-chunk as contiguous rows.
__global__ __launch_bounds__(128) void scan_kernel(
    const float* __restrict__ Alf, const float* __restrict__ Df,
    const float* __restrict__ Alb, const float* __restrict__ Db)
{
    const int bi   = blockIdx.x;         // 256 blocks: dir(2) x b(8) x dblk(16)
    const int dir  = bi >> 7;
    const int b    = (bi >> 4) & 7;
    const int dblk = bi & 15;
    const int tid  = threadIdx.x;
    const int w    = tid >> 5;
    const int lane = tid & 31;
    const int q    = lane >> 3;          // state quarter 0..3
    const int dlo  = lane & 7;
    const int dloc = w * 8 + dlo;        // local channel 0..31
    const int d    = dblk * 32 + dloc;

    const float* Al = dir ? Alb : Alf;
    const float* Dp = dir ? Db : Df;

    float A[4];
#pragma unroll
    for (int n = 0; n < 4; n++) A[n] = -__expf(Al[d * NST + q * 4 + n]);
    const float Dd = Dp[d];

    float h[4];
#pragma unroll
    for (int n = 0; n < 4; n++) h[n] = 0.f;

    const size_t mb = (size_t)dir * MROWS + (size_t)b * LSEQ;
    const float* __restrict__ dl  = g_delta + mb * DINNER + dblk * 32;
    const float* __restrict__ xp  = g_xc    + mb * DINNER + dblk * 32;
    const float* __restrict__ szp = g_sz    + mb * DINNER + dblk * 32;
    float* __restrict__ yTp = g_xi + ((size_t)(dir * DINNER + dblk * 32) * NB + b) * LSEQ;
    const float* __restrict__ bc  = g_xdbl  + mb * 48 + 16;   // [B(16)|C(16)]

    __shared__ float sBC[64][32];
    __shared__ float sD[64][32];
    __shared__ float sX[64][32];
    __shared__ float sS[64][32];
    __shared__ float sY[32][65];

    for (int t0 = 0; t0 < LSEQ; t0 += 64) {
        __syncthreads();
        // coalesced chunk loads: each row = 32 contiguous floats
#pragma unroll
        for (int i = 0; i < 16; i++) {
            int flat = tid + i * 128;        // 2048 = 64*32
            int tt = flat >> 5, j = flat & 31;
            size_t off = (size_t)(t0 + tt) * DINNER + j;
            sBC[tt][j] = bc[(size_t)(t0 + tt) * 48 + j];
            sD[tt][j]  = dl[off];
            sX[tt][j]  = xp[off];
            sS[tt][j]  = szp[off];
        }
        __syncthreads();
#pragma unroll 4
        for (int t = 0; t < 64; t++) {
            float dcur = sD[t][dloc];
            float xcur = sX[t][dloc];
            float4 Bv = *reinterpret_cast<const float4*>(&sBC[t][q * 4]);
            float4 Cv = *reinterpret_cast<const float4*>(&sBC[t][16 + q * 4]);

            const float dx = dcur * xcur;
            float y;
            h[0] = fmaf(__expf(dcur * A[0]), h[0], dx * Bv.x); y = h[0] * Cv.x;
            h[1] = fmaf(__expf(dcur * A[1]), h[1], dx * Bv.y); y = fmaf(h[1], Cv.y, y);
            h[2] = fmaf(__expf(dcur * A[2]), h[2], dx * Bv.z); y = fmaf(h[2], Cv.z, y);
            h[3] = fmaf(__expf(dcur * A[3]), h[3], dx * Bv.w); y = fmaf(h[3], Cv.w, y);

            y += __shfl_xor_sync(0xFFFFFFFFu, y, 8);
            y += __shfl_xor_sync(0xFFFFFFFFu, y, 16);

            if (q == 0)
                sY[dloc][t] = (y + xcur * Dd) * sS[t][dloc];
        }
        __syncthreads();
        // coalesced chunk store: row d -> 64 contiguous t
#pragma unroll
        for (int i = 0; i < 16; i++) {
            int flat = tid + i * 128;
            int drow = flat >> 6, col = flat & 63;
            yTp[(size_t)drow * (NB * LSEQ) + t0 + col] = sY[drow][col];
        }
    }
}

// ---------------- K5: out_w split prepass -----------------------------------
__global__ __launch_bounds__(256) void cvt_split_out(
    const float* __restrict__ fout, const float* __restrict__ bout)
{
    const int which = blockIdx.y;
    const float* __restrict__ src = which ? bout : fout;
    unsigned short* hi = g_woh[which];
    unsigned short* lo = g_wol[which];

    int i = blockIdx.x * 256 + threadIdx.x;   // 32768 float4s
    float4 v = reinterpret_cast<const float4*>(src)[i];
    unsigned short h0, h1, h2, h3, q0, q1, q2, q3;
    splitf_(v.x, h0, q0); splitf_(v.y, h1, q1);
    splitf_(v.z, h2, q2); splitf_(v.w, h3, q3);
    reinterpret_cast<uint2*>(hi)[i] =
        make_uint2((unsigned)h0 | ((unsigned)h1 << 16), (unsigned)h2 | ((unsigned)h3 << 16));
    reinterpret_cast<uint2*>(lo)[i] =
        make_uint2((unsigned)q0 | ((unsigned)q1 << 16), (unsigned)q2 | ((unsigned)q3 << 16));
}

// ---------------- K6: out-projection (tensor core) + un-flip + concat -------
// out[b, dir*256+o, l_phys] = sum_d yT[d, b, l] * W[o, d]
__global__ __launch_bounds__(256) void gemm_out_tc(float* __restrict__ out)
{
    const int dir = blockIdx.z;
    const int m0 = blockIdx.y * 128;
    const int n0 = blockIdx.x * 128;
    const int b  = m0 >> 11;
    const int l0 = m0 & (LSEQ - 1);
    const unsigned short* __restrict__ Wh = g_woh[dir];
    const unsigned short* __restrict__ Wl = g_wol[dir];

    __shared__ unsigned Ahp[16][136], Alp[16][136];
    __shared__ unsigned Bhp[128][20], Blp[128][20];

    const int tid = threadIdx.x;
    const int warp = tid >> 5, lane = tid & 31;
    const int wm = (warp & 3) * 32, wn = (warp >> 2) * 64;
    const int grp = lane >> 2, qid = lane & 3;

    float c[2][8][4];
#pragma unroll
    for (int mi = 0; mi < 2; mi++)
#pragma unroll
        for (int ni = 0; ni < 8; ni++)
#pragma unroll
            for (int r = 0; r < 4; r++) c[mi][ni][r] = 0.f;

    const int ak2   = tid >> 4;
    const int amseg = (tid & 15) * 8;
    const int bnrow = tid >> 1;
    const int bkseg = (tid & 1) * 8;

    for (int k0 = 0; k0 < DINNER; k0 += 32) {
        const float* srcE = g_xi +
            ((size_t)(dir * DINNER + k0 + 2 * ak2) * NB + b) * LSEQ + l0;
        const float* srcO = srcE + (size_t)NB * LSEQ;
#pragma unroll
        for (int j = 0; j < 2; j++) {
            int mofs = amseg + j * 4;
            float4 ve = *reinterpret_cast<const float4*>(srcE + mofs);
            float4 vo = *reinterpret_cast<const float4*>(srcO + mofs);
            unsigned short he[4], le[4], ho[4], lo_[4];
            splitf_(ve.x, he[0], le[0]); splitf_(ve.y, he[1], le[1]);
            splitf_(ve.z, he[2], le[2]); splitf_(ve.w, he[3], le[3]);
            splitf_(vo.x, ho[0], lo_[0]); splitf_(vo.y, ho[1], lo_[1]);
            splitf_(vo.z, ho[2], lo_[2]); splitf_(vo.w, ho[3], lo_[3]);
            uint4 ph, pl;
            ph.x = (unsigned)he[0] | ((unsigned)ho[0] << 16);
            ph.y = (unsigned)he[1] | ((unsigned)ho[1] << 16);
            ph.z = (unsigned)he[2] | ((unsigned)ho[2] << 16);
            ph.w = (unsigned)he[3] | ((unsigned)ho[3] << 16);
            pl.x = (unsigned)le[0] | ((unsigned)lo_[0] << 16);
            pl.y = (unsigned)le[1] | ((unsigned)lo_[1] << 16);
            pl.z = (unsigned)le[2] | ((unsigned)lo_[2] << 16);
            pl.w = (unsigned)le[3] | ((unsigned)lo_[3] << 16);
            *reinterpret_cast<uint4*>(&Ahp[ak2][mofs]) = ph;
            *reinterpret_cast<uint4*>(&Alp[ak2][mofs]) = pl;
        }
        {
            const unsigned short* wh = Wh + (size_t)(n0 + bnrow) * DINNER + k0 + bkseg * 2;
            const unsigned short* wl = Wl + (size_t)(n0 + bnrow) * DINNER + k0 + bkseg * 2;
            *reinterpret_cast<uint4*>(&Bhp[bnrow][bkseg]) = *reinterpret_cast<const uint4*>(wh);
            *reinterpret_cast<uint4*>(&Bhp[bnrow][bkseg + 4]) = *reinterpret_cast<const uint4*>(wh + 8);
            *reinterpret_cast<uint4*>(&Blp[bnrow][bkseg]) = *reinterpret_cast<const uint4*>(wl);
            *reinterpret_cast<uint4*>(&Blp[bnrow][bkseg + 4]) = *reinterpret_cast<const uint4*>(wl + 8);
        }
        __syncthreads();
#pragma unroll
        for (int kk = 0; kk < 2; kk++) {
            const int kq = kk * 8 + qid;
            unsigned bh[8][2], bl[8][2];
#pragma unroll
            for (int ni = 0; ni < 8; ni++) {
                int n = wn + ni * 8 + grp;
                bh[ni][0] = Bhp[n][kq];     bh[ni][1] = Bhp[n][kq + 4];
                bl[ni][0] = Blp[n][kq];     bl[ni][1] = Blp[n][kq + 4];
            }
#pragma unroll
            for (int mi = 0; mi < 2; mi++) {
                int m = wm + mi * 16 + grp;
                unsigned ah[4], al[4];
                ah[0] = Ahp[kq][m];     ah[1] = Ahp[kq][m + 8];
                ah[2] = Ahp[kq + 4][m]; ah[3] = Ahp[kq + 4][m + 8];
                al[0] = Alp[kq][m];     al[1] = Alp[kq][m + 8];
                al[2] = Alp[kq + 4][m]; al[3] = Alp[kq + 4][m + 8];
#pragma unroll
                for (int ni = 0; ni < 8; ni++) mma_bf16_(c[mi][ni], ah, bh[ni]);
#pragma unroll
                for (int ni = 0; ni < 8; ni++) mma_bf16_(c[mi][ni], ah, bl[ni]);
#pragma unroll
                for (int ni = 0; ni < 8; ni++) mma_bf16_(c[mi][ni], al, bh[ni]);
            }
        }
        __syncthreads();
    }

#pragma unroll
    for (int mi = 0; mi < 2; mi++) {
        int l = l0 + wm + mi * 16 + grp;
        int lp0 = dir ? (LSEQ - 1 - l) : l;
        int lp1 = dir ? (LSEQ - 1 - (l + 8)) : (l + 8);
#pragma unroll
        for (int ni = 0; ni < 8; ni++) {
            int o = n0 + wn + ni * 8 + qid * 2;
            float* op0 = out + ((size_t)b * (2 * DMODEL) + dir * DMODEL + o) * LSEQ;
            float* op1 = op0 + LSEQ;
            op0[lp0] = c[mi][ni][0];
            op1[lp0] = c[mi][ni][1];
            op0[lp1] = c[mi][ni][2];
            op1[lp1] = c[mi][ni][3];
        }
    }
}

// ---------------- launch -----------------------------------------------------
extern "C" void kernel_launch(void* const* d_in, const int* in_sizes, int n_in,
                              void* d_out, int out_size)
{
    (void)in_sizes; (void)n_in; (void)out_size;
    const float* x         = (const float*)d_in[0];
    const float* f_in_w    = (const float*)d_in[1];
    const float* f_conv_w  = (const float*)d_in[2];
    const float* f_conv_b  = (const float*)d_in[3];
    const float* f_xproj_w = (const float*)d_in[4];
    const float* f_dt_w    = (const float*)d_in[5];
    const float* f_dt_b    = (const float*)d_in[6];
    const float* f_A_log   = (const float*)d_in[7];
    const float* f_D       = (const float*)d_in[8];
    const float* f_out_w   = (const float*)d_in[9];
    const float* b_in_w    = (const float*)d_in[10];
    const float* b_conv_w  = (const float*)d_in[11];
    const float* b_conv_b  = (const float*)d_in[12];
    const float* b_xproj_w = (const float*)d_in[13];
    const float* b_dt_w    = (const float*)d_in[14];
    const float* b_dt_b    = (const float*)d_in[15];
    const float* b_A_log   = (const float*)d_in[16];
    const float* b_D       = (const float*)d_in[17];
    const float* b_out_w   = (const float*)d_in[18];
    float* out = (float*)d_out;

    gemm_in_tc        <<<dim3(8, 128, 2), 256>>>(x, f_in_w, b_in_w);
    conv_silu_kernel  <<<dim3(8, 8, 2),   512>>>(f_conv_w, f_conv_b, b_conv_w, b_conv_b);
    xproj_delta_kernel<<<dim3(128, 1, 2), 256>>>(f_xproj_w, b_xproj_w,
                                                 f_dt_w, f_dt_b, b_dt_w, b_dt_b);
    scan_kernel       <<<256, 128>>>(f_A_log, f_D, b_A_log, b_D);   // profiled slot 4
    cvt_split_out     <<<dim3(128, 2),    256>>>(f_out_w, b_out_w);
    gemm_out_tc       <<<dim3(2, 128, 2), 256>>>(out);
}